// round 13
// baseline (speedup 1.0000x reference)
#include <cuda_runtime.h>
#include <cuda_bf16.h>
#include <cuda_fp16.h>
#include <cstdint>

#define N_ENT  100000
#define NQ     64
#define NT     100064
#define D      128
#define HD     256
#define E_EDGE 400000
#define E_TOT  500000
#define R_REL  500
#define NEG    0.2f
#define NB     391            // ceil(N_ENT / 256)
#define SRCMASK 0x1FFFF       // 17 bits (NT < 2^17)

// ---------------- static device scratch ----------------
// Feature rows HEAD-INTERLEAVED: j = d*2 + h
__device__ __align__(16) __half g_xlh[(size_t)NT * HD];
__device__ __align__(16) __half g_xr[(size_t)NT * HD];
__device__ __align__(16) __half g_erel[(R_REL + 1) * HD];
__device__ __align__(16) float  g_atti[HD];
__device__ __nv_bfloat16 g_wh[512 * 128];
__device__ __nv_bfloat16 g_wl[512 * 128];
// CSR scratch
__device__ int g_deg[N_ENT];
__device__ int g_rowptr[N_ENT + 1];
__device__ int g_cur[N_ENT];
__device__ int g_bsum[NB];
__device__ int g_boff[NB];
__device__ uint2 g_csr[E_EDGE];             // (src | rel<<17, tgt) per CSR slot

// ---------------- helpers ----------------
__device__ __forceinline__ uint32_t smem_u32(const void* p) {
    uint32_t a;
    asm("{ .reg .u64 t; cvta.to.shared.u64 t, %1; cvt.u32.u64 %0, t; }" : "=r"(a) : "l"(p));
    return a;
}
__device__ __forceinline__ void ldsm_x4(uint32_t* r, uint32_t addr) {
    asm volatile("ldmatrix.sync.aligned.m8n8.x4.shared.b16 {%0,%1,%2,%3}, [%4];"
                 : "=r"(r[0]), "=r"(r[1]), "=r"(r[2]), "=r"(r[3]) : "r"(addr));
}
__device__ __forceinline__ void mma_bf16(float* d, const uint32_t* a, const uint32_t* b) {
    asm volatile("mma.sync.aligned.m16n8k16.row.col.f32.bf16.bf16.f32 "
                 "{%0,%1,%2,%3}, {%4,%5,%6,%7}, {%8,%9}, {%0,%1,%2,%3};"
                 : "+f"(d[0]), "+f"(d[1]), "+f"(d[2]), "+f"(d[3])
                 : "r"(a[0]), "r"(a[1]), "r"(a[2]), "r"(a[3]), "r"(b[0]), "r"(b[1]));
}
__device__ __forceinline__ void cp16(uint32_t dst, const void* src) {
    asm volatile("cp.async.cg.shared.global [%0], [%1], 16;" :: "r"(dst), "l"(src));
}

#define PLANE 32768
#define SM_AHI 0
#define SM_ALO PLANE
#define SM_B   (2 * PLANE)
#define SM_TOTAL (3 * PLANE)

// ---------------- split W into bf16 hi/lo (interleave permutation) ----------------
__global__ void k_wsplit(const float* __restrict__ Wl, const float* __restrict__ Wr) {
    int i = blockIdx.x * 256 + threadIdx.x;
    if (i >= 512 * 128) return;
    int n = i >> 7, k = i & 127;
    float v;
    if (n < 256) { int m = (n & 1) * 128 + (n >> 1); v = Wl[m * 128 + k]; }
    else         { int q = n - 256; int m = (q & 1) * 128 + (q >> 1); v = Wr[m * 128 + k]; }
    __nv_bfloat16 h = __float2bfloat16(v);
    g_wh[i] = h;
    g_wl[i] = __float2bfloat16(v - __bfloat162float(h));
}

__device__ __forceinline__ void load_b_tile(uint32_t sb, const __nv_bfloat16* w, int tid) {
#pragma unroll
    for (int i = 0; i < 8; ++i) {
        int j = i * 256 + tid;
        int r = j >> 4, c = j & 15;
        uint32_t dst = sb + SM_B + (uint32_t)(r * 256 + ((c ^ (r & 7)) << 4));
        cp16(dst, w + r * 128 + c * 8);
    }
    asm volatile("cp.async.commit_group;" ::: "memory");
}
#define CPWAIT() asm volatile("cp.async.wait_group 0;" ::: "memory")

// ---------------- HMMA GEMM (unchanged, known-good) ----------------
__global__ __launch_bounds__(256, 2) void k_gemm_mma(
    const float* __restrict__ ent, const float* __restrict__ qry,
    const float* __restrict__ bl, const float* __restrict__ br) {
    extern __shared__ char smem[];
    const uint32_t sb = smem_u32(smem);
    const int tid = threadIdx.x;
    const int wid = tid >> 5, lane = tid & 31;
    const int row0 = blockIdx.x * 128;

    load_b_tile(sb, g_wh, tid);

#pragma unroll
    for (int i = 0; i < 16; ++i) {
        int idx = i * 256 + tid;
        int r = idx >> 5, c4 = (idx & 31) * 4;
        int gr = row0 + r;
        float4 v = make_float4(0.f, 0.f, 0.f, 0.f);
        if (gr < N_ENT)   v = *(const float4*)(ent + (size_t)gr * D + c4);
        else if (gr < NT) v = *(const float4*)(qry + (size_t)(gr - N_ENT) * D + c4);
        float f[4] = {v.x, v.y, v.z, v.w};
        uint32_t h01 = 0, h23 = 0, l01 = 0, l23 = 0;
#pragma unroll
        for (int j = 0; j < 4; ++j) {
            __nv_bfloat16 hb = __float2bfloat16(f[j]);
            __nv_bfloat16 lb = __float2bfloat16(f[j] - __bfloat162float(hb));
            uint32_t hu = *(unsigned short*)&hb, lu = *(unsigned short*)&lb;
            if (j < 2) { h01 |= hu << (16 * j);       l01 |= lu << (16 * j); }
            else       { h23 |= hu << (16 * (j - 2)); l23 |= lu << (16 * (j - 2)); }
        }
        uint32_t off = (uint32_t)(r * 256 + (((c4 >> 3) ^ (r & 7)) << 4) + ((c4 & 4) ? 8 : 0));
        *(uint2*)(smem + SM_AHI + off) = make_uint2(h01, h23);
        *(uint2*)(smem + SM_ALO + off) = make_uint2(l01, l23);
    }

    const int wm = wid & 3;
    const int wn = wid >> 2;
    const int am = wm * 32 + (lane & 15);
    const int akc = (lane >> 4);
    const int bn = wn * 64 + ((lane >> 4) & 1) * 8 + (lane & 7);
    const int bkc = ((lane >> 3) & 1);
    const int gid = lane >> 2, tig = lane & 3;
    const uint32_t a0base = sb + SM_AHI + (uint32_t)(am * 256);
    const uint32_t a1base = sb + SM_AHI + (uint32_t)((am + 16) * 256);
    const int axor = am & 7;
    const uint32_t bbase = sb + SM_B + (uint32_t)(bn * 256);

    for (int t = 0; t < 4; ++t) {
        CPWAIT();
        __syncthreads();

        float acc[2][8][4];
#pragma unroll
        for (int a = 0; a < 2; ++a)
#pragma unroll
            for (int b = 0; b < 8; ++b)
#pragma unroll
                for (int c = 0; c < 4; ++c) acc[a][b][c] = 0.f;

#pragma unroll
        for (int ks = 0; ks < 8; ++ks) {
            uint32_t ach = (uint32_t)(((2 * ks + akc) ^ axor) << 4);
            uint32_t ah0[4], ah1[4], al0[4], al1[4];
            ldsm_x4(ah0, a0base + ach);
            ldsm_x4(al0, a0base + ach + PLANE);
            ldsm_x4(ah1, a1base + ach);
            ldsm_x4(al1, a1base + ach + PLANE);
#pragma unroll
            for (int ntp = 0; ntp < 4; ++ntp) {
                uint32_t baddr = bbase + (uint32_t)(ntp * 16 * 256 + (((2 * ks + bkc) ^ ((bn + ntp * 16) & 7)) << 4));
                uint32_t bh[4];
                ldsm_x4(bh, baddr);
                mma_bf16(acc[0][2 * ntp],     ah0, bh);
                mma_bf16(acc[0][2 * ntp],     al0, bh);
                mma_bf16(acc[0][2 * ntp + 1], ah0, bh + 2);
                mma_bf16(acc[0][2 * ntp + 1], al0, bh + 2);
                mma_bf16(acc[1][2 * ntp],     ah1, bh);
                mma_bf16(acc[1][2 * ntp],     al1, bh);
                mma_bf16(acc[1][2 * ntp + 1], ah1, bh + 2);
                mma_bf16(acc[1][2 * ntp + 1], al1, bh + 2);
            }
        }
        __syncthreads();

        load_b_tile(sb, g_wl + (size_t)t * 16384, tid);
        CPWAIT();
        __syncthreads();
#pragma unroll
        for (int ks = 0; ks < 8; ++ks) {
            uint32_t ach = (uint32_t)(((2 * ks + akc) ^ axor) << 4);
            uint32_t ah0[4], ah1[4];
            ldsm_x4(ah0, a0base + ach);
            ldsm_x4(ah1, a1base + ach);
#pragma unroll
            for (int ntp = 0; ntp < 4; ++ntp) {
                uint32_t baddr = bbase + (uint32_t)(ntp * 16 * 256 + (((2 * ks + bkc) ^ ((bn + ntp * 16) & 7)) << 4));
                uint32_t blo[4];
                ldsm_x4(blo, baddr);
                mma_bf16(acc[0][2 * ntp],     ah0, blo);
                mma_bf16(acc[0][2 * ntp + 1], ah0, blo + 2);
                mma_bf16(acc[1][2 * ntp],     ah1, blo);
                mma_bf16(acc[1][2 * ntp + 1], ah1, blo + 2);
            }
        }
        __syncthreads();
        if (t < 3) load_b_tile(sb, g_wh + (size_t)(t + 1) * 16384, tid);

#pragma unroll
        for (int mi = 0; mi < 2; ++mi) {
            int r1 = row0 + wm * 32 + mi * 16 + gid;
            int r2 = r1 + 8;
#pragma unroll
            for (int ni = 0; ni < 8; ++ni) {
                int cg = t * 128 + wn * 64 + ni * 8 + tig * 2;
                __half* base;
                const float* bb;
                int c;
                if (cg < HD) { base = g_xlh; c = cg;      bb = bl; }
                else         { base = g_xr;  c = cg - HD; bb = br; }
                int d = c >> 1;
                float bvx = bb[d], bvy = bb[128 + d];
                if (r1 < NT)
                    *(__half2*)(base + (size_t)r1 * HD + c) =
                        __floats2half2_rn(acc[mi][ni][0] + bvx, acc[mi][ni][1] + bvy);
                if (r2 < NT)
                    *(__half2*)(base + (size_t)r2 * HD + c) =
                        __floats2half2_rn(acc[mi][ni][2] + bvx, acc[mi][ni][3] + bvy);
            }
        }
    }
}

// ---------------- init: zero deg, interleave att ----------------
__global__ void k_zero(const float* __restrict__ att) {
    int i = blockIdx.x * 256 + threadIdx.x;
    if (i < N_ENT) g_deg[i] = 0;
    if (i < HD) g_atti[(i & 127) * 2 + (i >> 7)] = att[i];
}

// ---------------- CSR build ----------------
__global__ void k_count(const int* __restrict__ ei) {
    int e = blockIdx.x * 256 + threadIdx.x;
    if (e < E_EDGE) atomicAdd(&g_deg[ei[E_EDGE + e]], 1);
}
__global__ void k_scan1() {
    __shared__ int sm[256];
    int i = blockIdx.x * 256 + threadIdx.x;
    sm[threadIdx.x] = (i < N_ENT) ? g_deg[i] : 0;
    __syncthreads();
    for (int o = 128; o; o >>= 1) {
        if (threadIdx.x < o) sm[threadIdx.x] += sm[threadIdx.x + o];
        __syncthreads();
    }
    if (!threadIdx.x) g_bsum[blockIdx.x] = sm[0];
}
__global__ void k_scan2() {
    __shared__ int sm[512];
    int t = threadIdx.x;
    int v = (t < NB) ? g_bsum[t] : 0;
    sm[t] = v;
    __syncthreads();
    for (int o = 1; o < 512; o <<= 1) {
        int x = (t >= o) ? sm[t - o] : 0;
        __syncthreads();
        sm[t] += x;
        __syncthreads();
    }
    if (t < NB) g_boff[t] = sm[t] - v;
    if (!t) g_rowptr[N_ENT] = E_EDGE;
}
__global__ void k_scan3() {
    __shared__ int sm[256];
    int i = blockIdx.x * 256 + threadIdx.x;
    int tx = threadIdx.x;
    int v = (i < N_ENT) ? g_deg[i] : 0;
    sm[tx] = v;
    __syncthreads();
    for (int o = 1; o < 256; o <<= 1) {
        int x = (tx >= o) ? sm[tx - o] : 0;
        __syncthreads();
        sm[tx] += x;
        __syncthreads();
    }
    if (i < N_ENT) {
        int rp = g_boff[blockIdx.x] + sm[tx] - v;
        g_rowptr[i] = rp;
        g_cur[i] = rp;
    }
}
__global__ void k_scatter(const int* __restrict__ ei, const int* __restrict__ ridx) {
    int e = blockIdx.x * 256 + threadIdx.x;
    if (e >= E_EDGE) return;
    int t = ei[E_EDGE + e];
    int pos = atomicAdd(&g_cur[t], 1);
    g_csr[pos] = make_uint2((uint32_t)ei[e] | ((uint32_t)ridx[e] << 17), (uint32_t)t);
}

// ---------------- fused: e_rel (interleaved) + out_edge row ----------------
__global__ void k_rel_fused(const float* __restrict__ relations, const float* __restrict__ Wea,
                            const float* __restrict__ Wle, const float* __restrict__ ble,
                            float* __restrict__ out) {
    __shared__ float row[D];
    __shared__ float hid[HD];
    __shared__ float part[256];
    int r = blockIdx.x;
    int tid = threadIdx.x;
    if (tid < D) row[tid] = (r == R_REL) ? 1.f : relations[r * D + tid];
    __syncthreads();
    const float4* rv = (const float4*)row;
    const float4* wv = (const float4*)(Wea + (size_t)tid * D);
    float s = 0.f;
#pragma unroll
    for (int k = 0; k < D / 4; ++k) {
        float4 a = rv[k], b = wv[k];
        s += a.x * b.x + a.y * b.y + a.z * b.z + a.w * b.w;
    }
    g_erel[r * HD + (tid & 127) * 2 + (tid >> 7)] = __float2half(s);
    if (r == R_REL) return;
    hid[tid] = fmaxf(s, 0.f);
    __syncthreads();

    int col = tid & 127, half = tid >> 7;
    const float4* hv = (const float4*)(hid + half * 128);
    const float4* wlv = (const float4*)(Wle + (size_t)col * HD + half * 128);
    float p = 0.f;
#pragma unroll
    for (int k = 0; k < 32; ++k) {
        float4 a = hv[k], b = wlv[k];
        p += a.x * b.x + a.y * b.y + a.z * b.z + a.w * b.w;
    }
    part[tid] = p;
    __syncthreads();
    if (tid < 128)
        out[(size_t)N_ENT * D + r * D + tid] = part[tid] + part[tid + 128] + ble[tid];
}

// ---------------- single-pass fused edge kernel: warp = target ----------------
// U_h = sum_e p_e * xlh_e ; den_h = sum_e p_e ; out = 0.5*(U0/den0 + U1/den1) + bias
__global__ __launch_bounds__(256) void k_fused(const int* __restrict__ batch,
                                               const float* __restrict__ bias,
                                               float* __restrict__ out) {
    int gw = (blockIdx.x * 256 + threadIdx.x) >> 5;
    if (gw >= N_ENT) return;
    int lane = threadIdx.x & 31;

    int row = g_rowptr[gw];
    int deg = g_rowptr[gw + 1] - row;
    int ne = deg + 1;     // + self edge (last)
    uint32_t selfpk = (uint32_t)(N_ENT + batch[gw]) | ((uint32_t)R_REL << 17);
    const uint32_t* csrx = (const uint32_t*)g_csr;   // .x at even indices

    // xr row + att, once per target
    uint4 xv = ((const uint4*)g_xr)[(size_t)gw * 32 + lane];
    const uint32_t* xru = (const uint32_t*)&xv;
    float xrf[8];
#pragma unroll
    for (int k = 0; k < 4; ++k) {
        float2 a = __half22float2(*(const __half2*)&xru[k]);
        xrf[2 * k] = a.x; xrf[2 * k + 1] = a.y;
    }
    float4 at0 = ((const float4*)g_atti)[lane * 2];
    float4 at1 = ((const float4*)g_atti)[lane * 2 + 1];
    float atf[8] = {at0.x, at0.y, at0.z, at0.w, at1.x, at1.y, at1.z, at1.w};

    float acc0[4] = {0.f, 0.f, 0.f, 0.f};   // head0 (even halves)
    float acc1[4] = {0.f, 0.f, 0.f, 0.f};   // head1 (odd halves)
    float den0 = 0.f, den1 = 0.f;

    for (int c = 0; c < ne; c += 4) {
        int cnt = min(4, ne - c);
        uint4 ux[4], ue[4];
#pragma unroll
        for (int j = 0; j < 4; ++j) {
            if (j < cnt) {
                int e = c + j;
                uint32_t pk = (e < deg) ? csrx[2 * (row + e)] : selfpk;
                int src = pk & SRCMASK, rel = pk >> 17;
                ux[j] = ((const uint4*)g_xlh)[(size_t)src * 32 + lane];
                ue[j] = ((const uint4*)g_erel)[(size_t)rel * 32 + lane];
            }
        }
#pragma unroll
        for (int j = 0; j < 4; ++j) {
            if (j < cnt) {
                const uint32_t* au = (const uint32_t*)&ux[j];
                const uint32_t* eu = (const uint32_t*)&ue[j];
                float av0[4], av1[4];
                float s0 = 0.f, s1 = 0.f;
#pragma unroll
                for (int k = 0; k < 4; ++k) {
                    float2 a = __half22float2(*(const __half2*)&au[k]);
                    float2 cc = __half22float2(*(const __half2*)&eu[k]);
                    av0[k] = a.x; av1[k] = a.y;
                    float z0 = a.x + xrf[2 * k] + cc.x;
                    float z1 = a.y + xrf[2 * k + 1] + cc.y;
                    z0 = z0 > 0.f ? z0 : NEG * z0;
                    z1 = z1 > 0.f ? z1 : NEG * z1;
                    s0 += z0 * atf[2 * k];
                    s1 += z1 * atf[2 * k + 1];
                }
#pragma unroll
                for (int o = 16; o; o >>= 1) {
                    s0 += __shfl_xor_sync(0xffffffffu, s0, o);
                    s1 += __shfl_xor_sync(0xffffffffu, s1, o);
                }
                float p0 = expf(s0), p1 = expf(s1);
                den0 += p0; den1 += p1;
#pragma unroll
                for (int k = 0; k < 4; ++k) {
                    acc0[k] += p0 * av0[k];
                    acc1[k] += p1 * av1[k];
                }
            }
        }
    }
    float rd0 = 0.5f / (den0 + 1e-16f);
    float rd1 = 0.5f / (den1 + 1e-16f);
    float4 b4 = ((const float4*)bias)[lane];
    float4 o4;
    o4.x = acc0[0] * rd0 + acc1[0] * rd1 + b4.x;
    o4.y = acc0[1] * rd0 + acc1[1] * rd1 + b4.y;
    o4.z = acc0[2] * rd0 + acc1[2] * rd1 + b4.z;
    o4.w = acc0[3] * rd0 + acc1[3] * rd1 + b4.w;
    ((float4*)out)[(size_t)gw * 32 + lane] = o4;
}

// ---------------- launch: fork CSR/rel branch onto side stream ----------------
extern "C" void kernel_launch(void* const* d_in, const int* in_sizes, int n_in,
                              void* d_out, int out_size) {
    const float* queries        = (const float*)d_in[0];
    const float* entities       = (const float*)d_in[1];
    const int*   edge_index     = (const int*)d_in[2];
    const float* relations      = (const float*)d_in[3];
    const int*   relation_index = (const int*)d_in[4];
    const int*   batch          = (const int*)d_in[5];
    const float* W_l  = (const float*)d_in[6];
    const float* b_l  = (const float*)d_in[7];
    const float* W_r  = (const float*)d_in[8];
    const float* b_r  = (const float*)d_in[9];
    const float* W_ea = (const float*)d_in[10];
    const float* att  = (const float*)d_in[11];
    const float* bias = (const float*)d_in[12];
    const float* W_le = (const float*)d_in[13];
    const float* b_le = (const float*)d_in[14];
    float* out = (float*)d_out;

    static cudaStream_t s2 = nullptr;
    static cudaEvent_t evFork = nullptr, evJoin = nullptr;
    if (!s2) {
        cudaStreamCreateWithFlags(&s2, cudaStreamNonBlocking);
        cudaEventCreateWithFlags(&evFork, cudaEventDisableTiming);
        cudaEventCreateWithFlags(&evJoin, cudaEventDisableTiming);
    }

    // Fork: side branch = CSR build + rel/att prep (independent of GEMM)
    cudaEventRecord(evFork, 0);
    cudaStreamWaitEvent(s2, evFork, 0);
    k_zero<<<NB, 256, 0, s2>>>(att);
    k_rel_fused<<<R_REL + 1, 256, 0, s2>>>(relations, W_ea, W_le, b_le, out);
    k_count<<<(E_EDGE + 255) / 256, 256, 0, s2>>>(edge_index);
    k_scan1<<<NB, 256, 0, s2>>>();
    k_scan2<<<1, 512, 0, s2>>>();
    k_scan3<<<NB, 256, 0, s2>>>();
    k_scatter<<<(E_EDGE + 255) / 256, 256, 0, s2>>>(edge_index, relation_index);
    cudaEventRecord(evJoin, s2);

    // Main branch: weight split + GEMM
    k_wsplit<<<(512 * 128 + 255) / 256, 256>>>(W_l, W_r);
    cudaFuncSetAttribute(k_gemm_mma, cudaFuncAttributeMaxDynamicSharedMemorySize, SM_TOTAL);
    k_gemm_mma<<<(NT + 127) / 128, 256, SM_TOTAL>>>(entities, queries, b_l, b_r);

    // Join, then single-pass fused edge kernel
    cudaStreamWaitEvent(0, evJoin, 0);
    k_fused<<<(N_ENT * 32 + 255) / 256, 256>>>(batch, bias, out);
}

// round 14
// speedup vs baseline: 1.2208x; 1.2208x over previous
#include <cuda_runtime.h>
#include <cuda_bf16.h>
#include <cuda_fp16.h>
#include <cstdint>

#define N_ENT  100000
#define NQ     64
#define NT     100064
#define D      128
#define HD     256
#define E_EDGE 400000
#define E_TOT  500000
#define R_REL  500
#define NEG    0.2f
#define NB     391            // ceil(N_ENT / 256)
#define SRCMASK 0x1FFFF       // 17 bits (NT < 2^17)

// ---------------- static device scratch ----------------
// Feature rows HEAD-INTERLEAVED: j = d*2 + h
__device__ __align__(16) __half g_xlh[(size_t)NT * HD];
__device__ __align__(16) __half g_xr[(size_t)NT * HD];
__device__ __align__(16) __half g_erel[(R_REL + 1) * HD];
__device__ __align__(16) float  g_atti[HD];
__device__ __nv_bfloat16 g_wh[512 * 128];
__device__ __nv_bfloat16 g_wl[512 * 128];
__device__ __align__(16) float g_p[(size_t)E_TOT * 2];   // exp(logit), CSR order (+self tail)
// CSR scratch
__device__ int g_deg[N_ENT];
__device__ int g_rowptr[N_ENT + 1];
__device__ int g_cur[N_ENT];
__device__ int g_bsum[NB];
__device__ int g_boff[NB];
__device__ uint2 g_csr[E_EDGE];             // (src | rel<<17, tgt) per CSR slot

// ---------------- helpers ----------------
__device__ __forceinline__ uint32_t smem_u32(const void* p) {
    uint32_t a;
    asm("{ .reg .u64 t; cvta.to.shared.u64 t, %1; cvt.u32.u64 %0, t; }" : "=r"(a) : "l"(p));
    return a;
}
__device__ __forceinline__ void ldsm_x4(uint32_t* r, uint32_t addr) {
    asm volatile("ldmatrix.sync.aligned.m8n8.x4.shared.b16 {%0,%1,%2,%3}, [%4];"
                 : "=r"(r[0]), "=r"(r[1]), "=r"(r[2]), "=r"(r[3]) : "r"(addr));
}
__device__ __forceinline__ void mma_bf16(float* d, const uint32_t* a, const uint32_t* b) {
    asm volatile("mma.sync.aligned.m16n8k16.row.col.f32.bf16.bf16.f32 "
                 "{%0,%1,%2,%3}, {%4,%5,%6,%7}, {%8,%9}, {%0,%1,%2,%3};"
                 : "+f"(d[0]), "+f"(d[1]), "+f"(d[2]), "+f"(d[3])
                 : "r"(a[0]), "r"(a[1]), "r"(a[2]), "r"(a[3]), "r"(b[0]), "r"(b[1]));
}
__device__ __forceinline__ void cp16(uint32_t dst, const void* src) {
    asm volatile("cp.async.cg.shared.global [%0], [%1], 16;" :: "r"(dst), "l"(src));
}

#define PLANE 32768
#define SM_AHI 0
#define SM_ALO PLANE
#define SM_B   (2 * PLANE)
#define SM_TOTAL (3 * PLANE)

// ---------------- split W into bf16 hi/lo (interleave permutation) ----------------
__global__ void k_wsplit(const float* __restrict__ Wl, const float* __restrict__ Wr) {
    int i = blockIdx.x * 256 + threadIdx.x;
    if (i >= 512 * 128) return;
    int n = i >> 7, k = i & 127;
    float v;
    if (n < 256) { int m = (n & 1) * 128 + (n >> 1); v = Wl[m * 128 + k]; }
    else         { int q = n - 256; int m = (q & 1) * 128 + (q >> 1); v = Wr[m * 128 + k]; }
    __nv_bfloat16 h = __float2bfloat16(v);
    g_wh[i] = h;
    g_wl[i] = __float2bfloat16(v - __bfloat162float(h));
}

__device__ __forceinline__ void load_b_tile(uint32_t sb, const __nv_bfloat16* w, int tid) {
#pragma unroll
    for (int i = 0; i < 8; ++i) {
        int j = i * 256 + tid;
        int r = j >> 4, c = j & 15;
        uint32_t dst = sb + SM_B + (uint32_t)(r * 256 + ((c ^ (r & 7)) << 4));
        cp16(dst, w + r * 128 + c * 8);
    }
    asm volatile("cp.async.commit_group;" ::: "memory");
}
#define CPWAIT() asm volatile("cp.async.wait_group 0;" ::: "memory")

// ---------------- HMMA GEMM (unchanged, known-good) ----------------
__global__ __launch_bounds__(256, 2) void k_gemm_mma(
    const float* __restrict__ ent, const float* __restrict__ qry,
    const float* __restrict__ bl, const float* __restrict__ br) {
    extern __shared__ char smem[];
    const uint32_t sb = smem_u32(smem);
    const int tid = threadIdx.x;
    const int wid = tid >> 5, lane = tid & 31;
    const int row0 = blockIdx.x * 128;

    load_b_tile(sb, g_wh, tid);

#pragma unroll
    for (int i = 0; i < 16; ++i) {
        int idx = i * 256 + tid;
        int r = idx >> 5, c4 = (idx & 31) * 4;
        int gr = row0 + r;
        float4 v = make_float4(0.f, 0.f, 0.f, 0.f);
        if (gr < N_ENT)   v = *(const float4*)(ent + (size_t)gr * D + c4);
        else if (gr < NT) v = *(const float4*)(qry + (size_t)(gr - N_ENT) * D + c4);
        float f[4] = {v.x, v.y, v.z, v.w};
        uint32_t h01 = 0, h23 = 0, l01 = 0, l23 = 0;
#pragma unroll
        for (int j = 0; j < 4; ++j) {
            __nv_bfloat16 hb = __float2bfloat16(f[j]);
            __nv_bfloat16 lb = __float2bfloat16(f[j] - __bfloat162float(hb));
            uint32_t hu = *(unsigned short*)&hb, lu = *(unsigned short*)&lb;
            if (j < 2) { h01 |= hu << (16 * j);       l01 |= lu << (16 * j); }
            else       { h23 |= hu << (16 * (j - 2)); l23 |= lu << (16 * (j - 2)); }
        }
        uint32_t off = (uint32_t)(r * 256 + (((c4 >> 3) ^ (r & 7)) << 4) + ((c4 & 4) ? 8 : 0));
        *(uint2*)(smem + SM_AHI + off) = make_uint2(h01, h23);
        *(uint2*)(smem + SM_ALO + off) = make_uint2(l01, l23);
    }

    const int wm = wid & 3;
    const int wn = wid >> 2;
    const int am = wm * 32 + (lane & 15);
    const int akc = (lane >> 4);
    const int bn = wn * 64 + ((lane >> 4) & 1) * 8 + (lane & 7);
    const int bkc = ((lane >> 3) & 1);
    const int gid = lane >> 2, tig = lane & 3;
    const uint32_t a0base = sb + SM_AHI + (uint32_t)(am * 256);
    const uint32_t a1base = sb + SM_AHI + (uint32_t)((am + 16) * 256);
    const int axor = am & 7;
    const uint32_t bbase = sb + SM_B + (uint32_t)(bn * 256);

    for (int t = 0; t < 4; ++t) {
        CPWAIT();
        __syncthreads();

        float acc[2][8][4];
#pragma unroll
        for (int a = 0; a < 2; ++a)
#pragma unroll
            for (int b = 0; b < 8; ++b)
#pragma unroll
                for (int c = 0; c < 4; ++c) acc[a][b][c] = 0.f;

#pragma unroll
        for (int ks = 0; ks < 8; ++ks) {
            uint32_t ach = (uint32_t)(((2 * ks + akc) ^ axor) << 4);
            uint32_t ah0[4], ah1[4], al0[4], al1[4];
            ldsm_x4(ah0, a0base + ach);
            ldsm_x4(al0, a0base + ach + PLANE);
            ldsm_x4(ah1, a1base + ach);
            ldsm_x4(al1, a1base + ach + PLANE);
#pragma unroll
            for (int ntp = 0; ntp < 4; ++ntp) {
                uint32_t baddr = bbase + (uint32_t)(ntp * 16 * 256 + (((2 * ks + bkc) ^ ((bn + ntp * 16) & 7)) << 4));
                uint32_t bh[4];
                ldsm_x4(bh, baddr);
                mma_bf16(acc[0][2 * ntp],     ah0, bh);
                mma_bf16(acc[0][2 * ntp],     al0, bh);
                mma_bf16(acc[0][2 * ntp + 1], ah0, bh + 2);
                mma_bf16(acc[0][2 * ntp + 1], al0, bh + 2);
                mma_bf16(acc[1][2 * ntp],     ah1, bh);
                mma_bf16(acc[1][2 * ntp],     al1, bh);
                mma_bf16(acc[1][2 * ntp + 1], ah1, bh + 2);
                mma_bf16(acc[1][2 * ntp + 1], al1, bh + 2);
            }
        }
        __syncthreads();

        load_b_tile(sb, g_wl + (size_t)t * 16384, tid);
        CPWAIT();
        __syncthreads();
#pragma unroll
        for (int ks = 0; ks < 8; ++ks) {
            uint32_t ach = (uint32_t)(((2 * ks + akc) ^ axor) << 4);
            uint32_t ah0[4], ah1[4];
            ldsm_x4(ah0, a0base + ach);
            ldsm_x4(ah1, a1base + ach);
#pragma unroll
            for (int ntp = 0; ntp < 4; ++ntp) {
                uint32_t baddr = bbase + (uint32_t)(ntp * 16 * 256 + (((2 * ks + bkc) ^ ((bn + ntp * 16) & 7)) << 4));
                uint32_t blo[4];
                ldsm_x4(blo, baddr);
                mma_bf16(acc[0][2 * ntp],     ah0, blo);
                mma_bf16(acc[0][2 * ntp + 1], ah0, blo + 2);
                mma_bf16(acc[1][2 * ntp],     ah1, blo);
                mma_bf16(acc[1][2 * ntp + 1], ah1, blo + 2);
            }
        }
        __syncthreads();
        if (t < 3) load_b_tile(sb, g_wh + (size_t)(t + 1) * 16384, tid);

#pragma unroll
        for (int mi = 0; mi < 2; ++mi) {
            int r1 = row0 + wm * 32 + mi * 16 + gid;
            int r2 = r1 + 8;
#pragma unroll
            for (int ni = 0; ni < 8; ++ni) {
                int cg = t * 128 + wn * 64 + ni * 8 + tig * 2;
                __half* base;
                const float* bb;
                int c;
                if (cg < HD) { base = g_xlh; c = cg;      bb = bl; }
                else         { base = g_xr;  c = cg - HD; bb = br; }
                int d = c >> 1;
                float bvx = bb[d], bvy = bb[128 + d];
                if (r1 < NT)
                    *(__half2*)(base + (size_t)r1 * HD + c) =
                        __floats2half2_rn(acc[mi][ni][0] + bvx, acc[mi][ni][1] + bvy);
                if (r2 < NT)
                    *(__half2*)(base + (size_t)r2 * HD + c) =
                        __floats2half2_rn(acc[mi][ni][2] + bvx, acc[mi][ni][3] + bvy);
            }
        }
    }
}

// ---------------- init: zero deg, interleave att ----------------
__global__ void k_zero(const float* __restrict__ att) {
    int i = blockIdx.x * 256 + threadIdx.x;
    if (i < N_ENT) g_deg[i] = 0;
    if (i < HD) g_atti[(i & 127) * 2 + (i >> 7)] = att[i];
}

// ---------------- CSR build ----------------
__global__ void k_count(const int* __restrict__ ei) {
    int e = blockIdx.x * 256 + threadIdx.x;
    if (e < E_EDGE) atomicAdd(&g_deg[ei[E_EDGE + e]], 1);
}
__global__ void k_scan1() {
    __shared__ int sm[256];
    int i = blockIdx.x * 256 + threadIdx.x;
    sm[threadIdx.x] = (i < N_ENT) ? g_deg[i] : 0;
    __syncthreads();
    for (int o = 128; o; o >>= 1) {
        if (threadIdx.x < o) sm[threadIdx.x] += sm[threadIdx.x + o];
        __syncthreads();
    }
    if (!threadIdx.x) g_bsum[blockIdx.x] = sm[0];
}
__global__ void k_scan2() {
    __shared__ int sm[512];
    int t = threadIdx.x;
    int v = (t < NB) ? g_bsum[t] : 0;
    sm[t] = v;
    __syncthreads();
    for (int o = 1; o < 512; o <<= 1) {
        int x = (t >= o) ? sm[t - o] : 0;
        __syncthreads();
        sm[t] += x;
        __syncthreads();
    }
    if (t < NB) g_boff[t] = sm[t] - v;
    if (!t) g_rowptr[N_ENT] = E_EDGE;
}
__global__ void k_scan3() {
    __shared__ int sm[256];
    int i = blockIdx.x * 256 + threadIdx.x;
    int tx = threadIdx.x;
    int v = (i < N_ENT) ? g_deg[i] : 0;
    sm[tx] = v;
    __syncthreads();
    for (int o = 1; o < 256; o <<= 1) {
        int x = (tx >= o) ? sm[tx - o] : 0;
        __syncthreads();
        sm[tx] += x;
        __syncthreads();
    }
    if (i < N_ENT) {
        int rp = g_boff[blockIdx.x] + sm[tx] - v;
        g_rowptr[i] = rp;
        g_cur[i] = rp;
    }
}
__global__ void k_scatter(const int* __restrict__ ei, const int* __restrict__ ridx) {
    int e = blockIdx.x * 256 + threadIdx.x;
    if (e >= E_EDGE) return;
    int t = ei[E_EDGE + e];
    int pos = atomicAdd(&g_cur[t], 1);
    g_csr[pos] = make_uint2((uint32_t)ei[e] | ((uint32_t)ridx[e] << 17), (uint32_t)t);
}

// ---------------- fused: e_rel (interleaved) + out_edge row ----------------
__global__ void k_rel_fused(const float* __restrict__ relations, const float* __restrict__ Wea,
                            const float* __restrict__ Wle, const float* __restrict__ ble,
                            float* __restrict__ out) {
    __shared__ float row[D];
    __shared__ float hid[HD];
    __shared__ float part[256];
    int r = blockIdx.x;
    int tid = threadIdx.x;
    if (tid < D) row[tid] = (r == R_REL) ? 1.f : relations[r * D + tid];
    __syncthreads();
    const float4* rv = (const float4*)row;
    const float4* wv = (const float4*)(Wea + (size_t)tid * D);
    float s = 0.f;
#pragma unroll
    for (int k = 0; k < D / 4; ++k) {
        float4 a = rv[k], b = wv[k];
        s += a.x * b.x + a.y * b.y + a.z * b.z + a.w * b.w;
    }
    g_erel[r * HD + (tid & 127) * 2 + (tid >> 7)] = __float2half(s);
    if (r == R_REL) return;
    hid[tid] = fmaxf(s, 0.f);
    __syncthreads();

    int col = tid & 127, half = tid >> 7;
    const float4* hv = (const float4*)(hid + half * 128);
    const float4* wlv = (const float4*)(Wle + (size_t)col * HD + half * 128);
    float p = 0.f;
#pragma unroll
    for (int k = 0; k < 32; ++k) {
        float4 a = hv[k], b = wlv[k];
        p += a.x * b.x + a.y * b.y + a.z * b.z + a.w * b.w;
    }
    part[tid] = p;
    __syncthreads();
    if (tid < 128)
        out[(size_t)N_ENT * D + r * D + tid] = part[tid] + part[tid + 128] + ble[tid];
}

// ---------------- edge pass 1: logits, TWO edges per warp (6 gathers in flight) --
__global__ void k_logits(const int* __restrict__ batch) {
    int w = (blockIdx.x * blockDim.x + threadIdx.x) >> 5;
    int e0 = w * 2;                       // E_TOT even -> e0, e0+1 both valid
    if (e0 >= E_TOT) return;
    int lane = threadIdx.x & 31;

    int s[2], t[2], rel[2];
#pragma unroll
    for (int j = 0; j < 2; ++j) {
        int e = e0 + j;
        if (e < E_EDGE) {
            uint2 c = g_csr[e];
            s[j] = c.x & SRCMASK; rel[j] = c.x >> 17; t[j] = (int)c.y;
        } else {
            int i = e - E_EDGE;
            s[j] = N_ENT + batch[i]; t[j] = i; rel[j] = R_REL;
        }
    }

    // issue all 6 gathers up front
    uint4 av0 = ((const uint4*)g_xlh)[(size_t)s[0] * 32 + lane];
    uint4 av1 = ((const uint4*)g_xlh)[(size_t)s[1] * 32 + lane];
    uint4 bv0 = ((const uint4*)g_xr)[(size_t)t[0] * 32 + lane];
    uint4 bv1 = ((const uint4*)g_xr)[(size_t)t[1] * 32 + lane];
    uint4 cv0 = ((const uint4*)g_erel)[(size_t)rel[0] * 32 + lane];
    uint4 cv1 = ((const uint4*)g_erel)[(size_t)rel[1] * 32 + lane];
    float4 at0 = ((const float4*)g_atti)[lane * 2];
    float4 at1 = ((const float4*)g_atti)[lane * 2 + 1];
    float atf[8] = {at0.x, at0.y, at0.z, at0.w, at1.x, at1.y, at1.z, at1.w};

    float s00 = 0.f, s01 = 0.f, s10 = 0.f, s11 = 0.f;
    const uint32_t* au0 = (const uint32_t*)&av0;
    const uint32_t* bu0 = (const uint32_t*)&bv0;
    const uint32_t* cu0 = (const uint32_t*)&cv0;
    const uint32_t* au1 = (const uint32_t*)&av1;
    const uint32_t* bu1 = (const uint32_t*)&bv1;
    const uint32_t* cu1 = (const uint32_t*)&cv1;
#pragma unroll
    for (int k = 0; k < 4; ++k) {
        float2 a0 = __half22float2(*(const __half2*)&au0[k]);
        float2 b0 = __half22float2(*(const __half2*)&bu0[k]);
        float2 c0 = __half22float2(*(const __half2*)&cu0[k]);
        float z00 = a0.x + b0.x + c0.x;
        float z01 = a0.y + b0.y + c0.y;
        z00 = z00 > 0.f ? z00 : NEG * z00;
        z01 = z01 > 0.f ? z01 : NEG * z01;
        s00 += z00 * atf[2 * k];
        s01 += z01 * atf[2 * k + 1];

        float2 a1 = __half22float2(*(const __half2*)&au1[k]);
        float2 b1 = __half22float2(*(const __half2*)&bu1[k]);
        float2 c1 = __half22float2(*(const __half2*)&cu1[k]);
        float z10 = a1.x + b1.x + c1.x;
        float z11 = a1.y + b1.y + c1.y;
        z10 = z10 > 0.f ? z10 : NEG * z10;
        z11 = z11 > 0.f ? z11 : NEG * z11;
        s10 += z10 * atf[2 * k];
        s11 += z11 * atf[2 * k + 1];
    }
#pragma unroll
    for (int o = 16; o; o >>= 1) {
        s00 += __shfl_xor_sync(0xffffffffu, s00, o);
        s01 += __shfl_xor_sync(0xffffffffu, s01, o);
        s10 += __shfl_xor_sync(0xffffffffu, s10, o);
        s11 += __shfl_xor_sync(0xffffffffu, s11, o);
    }
    if (lane == 0) {
        float4 pv;
        pv.x = expf(s00);
        pv.y = expf(s01);
        pv.z = expf(s10);
        pv.w = expf(s11);
        *(float4*)(g_p + (size_t)e0 * 2) = pv;    // 16B-aligned (e0 even)
    }
}

// ---------------- edge pass 2: warp per target, no atomics, direct store --------
__global__ __launch_bounds__(256) void k_agg(const int* __restrict__ batch,
                                             const float* __restrict__ bias,
                                             float* __restrict__ out) {
    int gw = (blockIdx.x * 256 + threadIdx.x) >> 5;
    if (gw >= N_ENT) return;
    int lane = threadIdx.x & 31;

    int row = g_rowptr[gw];
    int deg = g_rowptr[gw + 1] - row;

    float2 selfp = ((const float2*)g_p)[E_EDGE + gw];

    float d0 = 0.f, d1 = 0.f;
    for (int j = lane; j < deg; j += 32) {
        float2 pv = ((const float2*)g_p)[row + j];
        d0 += pv.x; d1 += pv.y;
    }
#pragma unroll
    for (int o = 16; o; o >>= 1) {
        d0 += __shfl_xor_sync(0xffffffffu, d0, o);
        d1 += __shfl_xor_sync(0xffffffffu, d1, o);
    }
    d0 += selfp.x; d1 += selfp.y;
    float rd0 = 0.5f / (d0 + 1e-16f);
    float rd1 = 0.5f / (d1 + 1e-16f);

    float4 acc = make_float4(0.f, 0.f, 0.f, 0.f);
    for (int c = 0; c < deg; c += 4) {
        int cnt = min(4, deg - c);
        uint4 ux[4];
        float2 pp[4];
#pragma unroll
        for (int j = 0; j < 4; ++j) {
            if (j < cnt) {
                int src = (int)(g_csr[row + c + j].x & SRCMASK);
                ux[j] = ((const uint4*)g_xlh)[(size_t)src * 32 + lane];
                pp[j] = ((const float2*)g_p)[row + c + j];
            }
        }
#pragma unroll
        for (int j = 0; j < 4; ++j) {
            if (j < cnt) {
                float w0 = pp[j].x * rd0, w1 = pp[j].y * rd1;
                const uint32_t* xu = (const uint32_t*)&ux[j];
                float2 a0 = __half22float2(*(const __half2*)&xu[0]);
                float2 a1 = __half22float2(*(const __half2*)&xu[1]);
                float2 a2 = __half22float2(*(const __half2*)&xu[2]);
                float2 a3 = __half22float2(*(const __half2*)&xu[3]);
                acc.x += w0 * a0.x + w1 * a0.y;
                acc.y += w0 * a1.x + w1 * a1.y;
                acc.z += w0 * a2.x + w1 * a2.y;
                acc.w += w0 * a3.x + w1 * a3.y;
            }
        }
    }
    {
        int src = N_ENT + batch[gw];
        uint4 xv = ((const uint4*)g_xlh)[(size_t)src * 32 + lane];
        const uint32_t* xu = (const uint32_t*)&xv;
        float w0 = selfp.x * rd0, w1 = selfp.y * rd1;
        float2 a0 = __half22float2(*(const __half2*)&xu[0]);
        float2 a1 = __half22float2(*(const __half2*)&xu[1]);
        float2 a2 = __half22float2(*(const __half2*)&xu[2]);
        float2 a3 = __half22float2(*(const __half2*)&xu[3]);
        acc.x += w0 * a0.x + w1 * a0.y;
        acc.y += w0 * a1.x + w1 * a1.y;
        acc.z += w0 * a2.x + w1 * a2.y;
        acc.w += w0 * a3.x + w1 * a3.y;
    }
    float4 b4 = ((const float4*)bias)[lane];
    ((float4*)out)[(size_t)gw * 32 + lane] =
        make_float4(acc.x + b4.x, acc.y + b4.y, acc.z + b4.z, acc.w + b4.w);
}

// ---------------- launch: fork CSR/rel branch onto side stream ----------------
extern "C" void kernel_launch(void* const* d_in, const int* in_sizes, int n_in,
                              void* d_out, int out_size) {
    const float* queries        = (const float*)d_in[0];
    const float* entities       = (const float*)d_in[1];
    const int*   edge_index     = (const int*)d_in[2];
    const float* relations      = (const float*)d_in[3];
    const int*   relation_index = (const int*)d_in[4];
    const int*   batch          = (const int*)d_in[5];
    const float* W_l  = (const float*)d_in[6];
    const float* b_l  = (const float*)d_in[7];
    const float* W_r  = (const float*)d_in[8];
    const float* b_r  = (const float*)d_in[9];
    const float* W_ea = (const float*)d_in[10];
    const float* att  = (const float*)d_in[11];
    const float* bias = (const float*)d_in[12];
    const float* W_le = (const float*)d_in[13];
    const float* b_le = (const float*)d_in[14];
    float* out = (float*)d_out;

    static cudaStream_t s2 = nullptr;
    static cudaEvent_t evFork = nullptr, evJoin = nullptr;
    if (!s2) {
        cudaStreamCreateWithFlags(&s2, cudaStreamNonBlocking);
        cudaEventCreateWithFlags(&evFork, cudaEventDisableTiming);
        cudaEventCreateWithFlags(&evJoin, cudaEventDisableTiming);
    }

    // Fork: side branch = CSR build + rel/att prep (independent of GEMM)
    cudaEventRecord(evFork, 0);
    cudaStreamWaitEvent(s2, evFork, 0);
    k_zero<<<NB, 256, 0, s2>>>(att);
    k_rel_fused<<<R_REL + 1, 256, 0, s2>>>(relations, W_ea, W_le, b_le, out);
    k_count<<<(E_EDGE + 255) / 256, 256, 0, s2>>>(edge_index);
    k_scan1<<<NB, 256, 0, s2>>>();
    k_scan2<<<1, 512, 0, s2>>>();
    k_scan3<<<NB, 256, 0, s2>>>();
    k_scatter<<<(E_EDGE + 255) / 256, 256, 0, s2>>>(edge_index, relation_index);
    cudaEventRecord(evJoin, s2);

    // Main branch: weight split + GEMM
    k_wsplit<<<(512 * 128 + 255) / 256, 256>>>(W_l, W_r);
    cudaFuncSetAttribute(k_gemm_mma, cudaFuncAttributeMaxDynamicSharedMemorySize, SM_TOTAL);
    k_gemm_mma<<<(NT + 127) / 128, 256, SM_TOTAL>>>(entities, queries, b_l, b_r);

    // Join, then edge phase
    cudaStreamWaitEvent(0, evJoin, 0);
    int lw = (E_TOT / 2) * 32;                 // 250K warps, 2 edges each
    k_logits<<<(lw + 255) / 256, 256>>>(batch);
    k_agg<<<(N_ENT * 32 + 255) / 256, 256>>>(batch, bias, out);
}